// round 3
// baseline (speedup 1.0000x reference)
#include <cuda_runtime.h>

#define R     5
#define TILE  32
#define HT    42          // TILE + 2*R
#define NIMG  48          // 16 batch * 3 channels (depthwise -> independent planes)

typedef unsigned long long ull;

// Normalized 11-tap Gaussian (sigma=1.5) as compile-time literals
__device__ __forceinline__ float gw(int t) {
    constexpr float W[11] = {
        0.00102838f, 0.00759876f, 0.03600075f, 0.10936071f, 0.21300558f,
        0.26601173f,
        0.21300558f, 0.10936071f, 0.03600075f, 0.00759876f, 0.00102838f
    };
    return W[t];
}

// ---- f32x2 packed helpers (sm_100+) ----
__device__ __forceinline__ ull pk2(float a, float b) {
    ull r; asm("mov.b64 %0, {%1,%2};" : "=l"(r) : "f"(a), "f"(b)); return r;
}
__device__ __forceinline__ float2 upk2(ull v) {
    float2 r; asm("mov.b64 {%0,%1}, %2;" : "=f"(r.x), "=f"(r.y) : "l"(v)); return r;
}
__device__ __forceinline__ ull fma2(ull a, ull b, ull c) {
    ull d; asm("fma.rn.f32x2 %0, %1, %2, %3;" : "=l"(d) : "l"(a), "l"(b), "l"(c)); return d;
}
__device__ __forceinline__ ull mul2(ull a, ull b) {
    ull d; asm("mul.rn.f32x2 %0, %1, %2;" : "=l"(d) : "l"(a), "l"(b)); return d;
}
__device__ __forceinline__ ull wp(int t) { return pk2(gw(t), gw(t)); }

// Scratch pyramids (ping-pong between A and B)
__device__ float  g_bufAx[NIMG * 256 * 256];
__device__ float  g_bufAy[NIMG * 256 * 256];
__device__ float  g_bufBx[NIMG * 128 * 128];
__device__ float  g_bufBy[NIMG * 128 * 128];
__device__ double g_acc[5];

__global__ void zero_acc_kernel() {
    if (threadIdx.x < 5) g_acc[threadIdx.x] = 0.0;
}

// Fused per-level SSIM + optional 2x2 avg-pool for the next level.
// Pass 1 (vertical blur): conv streams packed f32x2: (x,y), (x^2,y^2), xy scalar.
// Pass 2 (horizontal blur): same packing, then SSIM + block reduction.
template<int BS, bool POOL>
__global__ __launch_bounds__(BS, (BS == 256 ? 5 : 3)) void ssim_level_kernel(
    const float* __restrict__ X, const float* __restrict__ Y,
    int H, int W, double* __restrict__ acc,
    float* __restrict__ PX, float* __restrict__ PY)
{
    __shared__ float2 sxy[HT][43];       // (x, y) interleaved
    __shared__ float2 hbmu[TILE][44];    // vertical-blurred (x, y)
    __shared__ float2 hbsq[TILE][44];    // vertical-blurred (x^2, y^2)
    __shared__ float  hbxy[TILE][44];    // vertical-blurred x*y
    __shared__ float  wsum[BS / 32];

    const int tid  = threadIdx.x;
    const int img  = blockIdx.z;
    const int base = img * H * W;
    const int r0   = blockIdx.y * TILE - R;
    const int c0   = blockIdx.x * TILE - R;

    // ---- load tile + halo (zero padding outside image) ----
    for (int i = tid; i < HT * HT; i += BS) {
        int r  = i / HT, c = i - r * HT;
        int gr = r0 + r, gc = c0 + c;
        float xv = 0.0f, yv = 0.0f;
        if ((unsigned)gr < (unsigned)H && (unsigned)gc < (unsigned)W) {
            int gi = base + gr * W + gc;
            xv = X[gi];
            yv = Y[gi];
        }
        sxy[r][c] = make_float2(xv, yv);
    }
    __syncthreads();

    // ---- fused 2x2 avg-pool of central 32x32 (input for next level) ----
    if (POOL && tid < 256) {
        int pr = tid >> 4, pc = tid & 15;
        int rr = R + 2 * pr, cc = R + 2 * pc;
        float2 a = sxy[rr][cc],     b = sxy[rr][cc + 1];
        float2 c = sxy[rr + 1][cc], d = sxy[rr + 1][cc + 1];
        int Ho = H >> 1, Wo = W >> 1;
        int o  = img * Ho * Wo + (blockIdx.y * 16 + pr) * Wo + blockIdx.x * 16 + pc;
        PX[o] = 0.25f * (a.x + b.x + c.x + d.x);
        PY[o] = 0.25f * (a.y + b.y + c.y + d.y);
    }

    // ---- pass 1: vertical blur, 4 output rows per unit, 42 cols x 8 quads ----
    for (int u = tid; u < HT * 8; u += BS) {
        int c  = u % HT;
        int rb = (u / HT) * 4;
        ull  amu[4] = {0, 0, 0, 0};
        ull  asq[4] = {0, 0, 0, 0};
        float axy[4] = {0.f, 0.f, 0.f, 0.f};
#pragma unroll
        for (int t = 0; t < 14; t++) {
            ull vxy = *(const ull*)&sxy[rb + t][c];
            ull vsq = mul2(vxy, vxy);
            float2 f = upk2(vxy);
            float vp = f.x * f.y;
#pragma unroll
            for (int k = 0; k < 4; k++) {
                int tt = t - k;                 // compile-time after unroll
                if (tt >= 0 && tt <= 10) {
                    amu[k] = fma2(wp(tt), vxy, amu[k]);
                    asq[k] = fma2(wp(tt), vsq, asq[k]);
                    axy[k] += gw(tt) * vp;
                }
            }
        }
#pragma unroll
        for (int k = 0; k < 4; k++) {
            *(ull*)&hbmu[rb + k][c] = amu[k];
            *(ull*)&hbsq[rb + k][c] = asq[k];
            hbxy[rb + k][c] = axy[k];
        }
    }
    __syncthreads();

    // ---- pass 2: horizontal blur + SSIM, 4 px/thread, stream-at-a-time ----
    float lsum = 0.f;
    if (tid < 256) {
        const int vr = tid >> 3;          // output row 0..31
        const int vc = (tid & 7) * 4;     // output col group

        float mu1[4], mu2[4], ex2[4], ey2[4], exy[4];

        {   // (mu1, mu2) stream
            ull acc2[4] = {0, 0, 0, 0};
            ull v[14];
#pragma unroll
            for (int t = 0; t < 14; t++) v[t] = *(const ull*)&hbmu[vr][vc + t];
#pragma unroll
            for (int t = 0; t < 14; t++)
#pragma unroll
                for (int k = 0; k < 4; k++) {
                    int tt = t - k;
                    if (tt >= 0 && tt <= 10) acc2[k] = fma2(wp(tt), v[t], acc2[k]);
                }
#pragma unroll
            for (int k = 0; k < 4; k++) { float2 f = upk2(acc2[k]); mu1[k] = f.x; mu2[k] = f.y; }
        }
        {   // (E[x^2], E[y^2]) stream
            ull acc2[4] = {0, 0, 0, 0};
            ull v[14];
#pragma unroll
            for (int t = 0; t < 14; t++) v[t] = *(const ull*)&hbsq[vr][vc + t];
#pragma unroll
            for (int t = 0; t < 14; t++)
#pragma unroll
                for (int k = 0; k < 4; k++) {
                    int tt = t - k;
                    if (tt >= 0 && tt <= 10) acc2[k] = fma2(wp(tt), v[t], acc2[k]);
                }
#pragma unroll
            for (int k = 0; k < 4; k++) { float2 f = upk2(acc2[k]); ex2[k] = f.x; ey2[k] = f.y; }
        }
        {   // E[xy] scalar stream (float4 row reads)
            float accs[4] = {0.f, 0.f, 0.f, 0.f};
            float v[16];
#pragma unroll
            for (int q = 0; q < 4; q++) {
                float4 a = *(const float4*)&hbxy[vr][vc + 4 * q];
                v[4 * q] = a.x; v[4 * q + 1] = a.y; v[4 * q + 2] = a.z; v[4 * q + 3] = a.w;
            }
#pragma unroll
            for (int t = 0; t < 14; t++)
#pragma unroll
                for (int k = 0; k < 4; k++) {
                    int tt = t - k;
                    if (tt >= 0 && tt <= 10) accs[k] += gw(tt) * v[t];
                }
#pragma unroll
            for (int k = 0; k < 4; k++) exy[k] = accs[k];
        }

        const float C1 = 4.0e-4f;   // (0.01*2)^2
        const float C2 = 3.6e-3f;   // (0.03*2)^2
#pragma unroll
        for (int k = 0; k < 4; k++) {
            float m1 = mu1[k], m2 = mu2[k];
            float m1sq = m1 * m1;
            float m2sq = m2 * m2;
            float m12  = m1 * m2;
            float s1c  = ex2[k] - m1sq;
            float s2c  = ey2[k] - m2sq;
            float s12  = exy[k] - m12;
            float num  = (2.f * m12 + C1) * (2.f * s12 + C2);
            float den  = (m1sq + m2sq + C1) * (s1c + s2c + C2);
            lsum += __fdividef(num, den + 1e-8f);
        }
    }

    // ---- block reduction -> one double atomic per block ----
#pragma unroll
    for (int o = 16; o > 0; o >>= 1)
        lsum += __shfl_xor_sync(0xFFFFFFFFu, lsum, o);
    if ((tid & 31) == 0) wsum[tid >> 5] = lsum;
    __syncthreads();
    if (tid == 0) {
        float b = 0.f;
#pragma unroll
        for (int i = 0; i < BS / 32; i++) b += wsum[i];
        atomicAdd(acc, (double)b);
    }
}

__global__ void finish_kernel(float* __restrict__ out) {
    const double w[5] = {0.0448, 0.2856, 0.3001, 0.2363, 0.1333};
    const double wsumv = 1.0001;  // reference normalizes by the weight sum
    double cnt = (double)NIMG * 512.0 * 512.0;
    double m = 0.0;
#pragma unroll
    for (int l = 0; l < 5; l++) {
        m += (w[l] / wsumv) * (g_acc[l] / cnt);
        cnt *= 0.25;
    }
    out[0] = (float)(1.0 - m);
}

extern "C" void kernel_launch(void* const* d_in, const int* in_sizes, int n_in,
                              void* d_out, int out_size)
{
    (void)in_sizes; (void)n_in; (void)out_size;
    const float* pred   = (const float*)d_in[0];
    const float* target = (const float*)d_in[1];
    float* out = (float*)d_out;

    float *bAx, *bAy, *bBx, *bBy;
    double* acc;
    cudaGetSymbolAddress((void**)&bAx, g_bufAx);
    cudaGetSymbolAddress((void**)&bAy, g_bufAy);
    cudaGetSymbolAddress((void**)&bBx, g_bufBx);
    cudaGetSymbolAddress((void**)&bBy, g_bufBy);
    cudaGetSymbolAddress((void**)&acc, g_acc);

    zero_acc_kernel<<<1, 32>>>();

    // L0 512^2 : SSIM + pool -> A (256^2)
    ssim_level_kernel<256, true ><<<dim3(16, 16, NIMG), 256>>>(pred, target, 512, 512, acc + 0, bAx, bAy);
    // L1 256^2 : SSIM + pool -> B (128^2)
    ssim_level_kernel<256, true ><<<dim3(8, 8, NIMG), 256>>>(bAx, bAy, 256, 256, acc + 1, bBx, bBy);
    // L2 128^2 : SSIM + pool -> A (64^2)  — 384-thread blocks: 1 pass-1 unit/thread
    ssim_level_kernel<384, true ><<<dim3(4, 4, NIMG), 384>>>(bBx, bBy, 128, 128, acc + 2, bAx, bAy);
    // L3 64^2  : SSIM + pool -> B (32^2)
    ssim_level_kernel<384, true ><<<dim3(2, 2, NIMG), 384>>>(bAx, bAy, 64, 64, acc + 3, bBx, bBy);
    // L4 32^2  : SSIM only
    ssim_level_kernel<384, false><<<dim3(1, 1, NIMG), 384>>>(bBx, bBy, 32, 32, acc + 4, nullptr, nullptr);

    finish_kernel<<<1, 1>>>(out);
}

// round 4
// speedup vs baseline: 1.0657x; 1.0657x over previous
#include <cuda_runtime.h>

#define R     5
#define TILE  32
#define HT    42          // TILE + 2*R
#define NIMG  48          // 16 batch * 3 channels (depthwise -> independent planes)

// Normalized 11-tap Gaussian (sigma=1.5) as compile-time literals
__device__ __forceinline__ float gw(int t) {
    constexpr float W[11] = {
        0.00102838f, 0.00759876f, 0.03600075f, 0.10936071f, 0.21300558f,
        0.26601173f,
        0.21300558f, 0.10936071f, 0.03600075f, 0.00759876f, 0.00102838f
    };
    return W[t];
}

// Pyramid buffers: A=256^2 (L1), B=128^2 (L2), C=64^2 (L3), D=32^2 (L4)
__device__ float  g_bufAx[NIMG * 256 * 256];
__device__ float  g_bufAy[NIMG * 256 * 256];
__device__ float  g_bufBx[NIMG * 128 * 128];
__device__ float  g_bufBy[NIMG * 128 * 128];
__device__ float  g_bufCx[NIMG * 64 * 64];
__device__ float  g_bufCy[NIMG * 64 * 64];
__device__ float  g_bufDx[NIMG * 32 * 32];
__device__ float  g_bufDy[NIMG * 32 * 32];
__device__ double g_acc[5];

__global__ void zero_acc_kernel() {
    if (threadIdx.x < 5) g_acc[threadIdx.x] = 0.0;
}

// One 32x32 SSIM tile: load (+halo), vertical blur (2-row units, balanced),
// horizontal blur (LDS.128 on paired fields), SSIM, block reduction.
template<bool POOL>
__device__ __forceinline__ void ssim_tile(
    const float* __restrict__ X, const float* __restrict__ Y,
    int H, int W, int tx, int ty, int img,
    double* __restrict__ acc,
    float* __restrict__ PX, float* __restrict__ PY)
{
    __shared__ __align__(16) float2 sxy[HT][43];     // (x, y) interleaved
    __shared__ __align__(16) float2 hbmu[TILE][44];  // v-blurred (x, y)
    __shared__ __align__(16) float2 hbsq[TILE][44];  // v-blurred (x^2, y^2)
    __shared__ __align__(16) float  hbxy[TILE][44];  // v-blurred x*y
    __shared__ float wsum[8];

    const int tid  = threadIdx.x;
    const int base = img * H * W;
    const int r0   = ty * TILE - R;
    const int c0   = tx * TILE - R;

    // ---- load tile + halo (zero padding outside image) ----
    for (int i = tid; i < HT * HT; i += 256) {
        int r  = i / HT, c = i - r * HT;
        int gr = r0 + r, gc = c0 + c;
        float xv = 0.0f, yv = 0.0f;
        if ((unsigned)gr < (unsigned)H && (unsigned)gc < (unsigned)W) {
            int gi = base + gr * W + gc;
            xv = X[gi];
            yv = Y[gi];
        }
        sxy[r][c] = make_float2(xv, yv);
    }
    __syncthreads();

    // ---- fused 2x2 avg-pool of the central 32x32 (next level's input) ----
    if (POOL) {
        int pr = tid >> 4, pc = tid & 15;
        int rr = R + 2 * pr, cc = R + 2 * pc;
        float2 a = sxy[rr][cc],     b = sxy[rr][cc + 1];
        float2 c = sxy[rr + 1][cc], d = sxy[rr + 1][cc + 1];
        int Ho = H >> 1, Wo = W >> 1;
        int o  = img * Ho * Wo + (ty * 16 + pr) * Wo + tx * 16 + pc;
        PX[o] = 0.25f * (a.x + b.x + c.x + d.x);
        PY[o] = 0.25f * (a.y + b.y + c.y + d.y);
    }

    // ---- pass 1: vertical blur, 2 output rows per unit (672 units) ----
    for (int u = tid; u < HT * 16; u += 256) {
        int c  = u % HT;
        int rb = (u / HT) * 2;
        float a0[2] = {0.f, 0.f}, a1[2] = {0.f, 0.f}, a2[2] = {0.f, 0.f};
        float a3[2] = {0.f, 0.f}, a4[2] = {0.f, 0.f};
#pragma unroll
        for (int t = 0; t < 12; t++) {
            float2 v = sxy[rb + t][c];
            float x2 = v.x * v.x, y2 = v.y * v.y, xy = v.x * v.y;
#pragma unroll
            for (int k = 0; k < 2; k++) {
                int tt = t - k;                 // compile-time after unroll
                if (tt >= 0 && tt <= 10) {
                    float w = gw(tt);
                    a0[k] += w * v.x;
                    a1[k] += w * v.y;
                    a2[k] += w * x2;
                    a3[k] += w * y2;
                    a4[k] += w * xy;
                }
            }
        }
#pragma unroll
        for (int k = 0; k < 2; k++) {
            hbmu[rb + k][c] = make_float2(a0[k], a1[k]);
            hbsq[rb + k][c] = make_float2(a2[k], a3[k]);
            hbxy[rb + k][c] = a4[k];
        }
    }
    __syncthreads();

    // ---- pass 2: horizontal blur + SSIM, 4 px/thread ----
    const int vr = tid >> 3;          // output row 0..31
    const int vc = (tid & 7) * 4;     // output col group (16B aligned)

    float mu1[4] = {0.f, 0.f, 0.f, 0.f}, mu2[4] = {0.f, 0.f, 0.f, 0.f};
    float ex2[4] = {0.f, 0.f, 0.f, 0.f}, ey2[4] = {0.f, 0.f, 0.f, 0.f};
    float exy[4] = {0.f, 0.f, 0.f, 0.f};

    {   // (mu1, mu2) stream — 7 x LDS.128
        float2 v[14];
        const float4* p = (const float4*)&hbmu[vr][vc];
#pragma unroll
        for (int q = 0; q < 7; q++) {
            float4 a = p[q];
            v[2 * q]     = make_float2(a.x, a.y);
            v[2 * q + 1] = make_float2(a.z, a.w);
        }
#pragma unroll
        for (int t = 0; t < 14; t++)
#pragma unroll
            for (int k = 0; k < 4; k++) {
                int tt = t - k;
                if (tt >= 0 && tt <= 10) {
                    mu1[k] += gw(tt) * v[t].x;
                    mu2[k] += gw(tt) * v[t].y;
                }
            }
    }
    {   // (E[x^2], E[y^2]) stream — 7 x LDS.128
        float2 v[14];
        const float4* p = (const float4*)&hbsq[vr][vc];
#pragma unroll
        for (int q = 0; q < 7; q++) {
            float4 a = p[q];
            v[2 * q]     = make_float2(a.x, a.y);
            v[2 * q + 1] = make_float2(a.z, a.w);
        }
#pragma unroll
        for (int t = 0; t < 14; t++)
#pragma unroll
            for (int k = 0; k < 4; k++) {
                int tt = t - k;
                if (tt >= 0 && tt <= 10) {
                    ex2[k] += gw(tt) * v[t].x;
                    ey2[k] += gw(tt) * v[t].y;
                }
            }
    }
    {   // E[xy] stream — 4 x LDS.128
        float v[16];
        const float4* p = (const float4*)&hbxy[vr][vc];
#pragma unroll
        for (int q = 0; q < 4; q++) {
            float4 a = p[q];
            v[4 * q] = a.x; v[4 * q + 1] = a.y; v[4 * q + 2] = a.z; v[4 * q + 3] = a.w;
        }
#pragma unroll
        for (int t = 0; t < 14; t++)
#pragma unroll
            for (int k = 0; k < 4; k++) {
                int tt = t - k;
                if (tt >= 0 && tt <= 10) exy[k] += gw(tt) * v[t];
            }
    }

    const float C1 = 4.0e-4f;   // (0.01*2)^2
    const float C2 = 3.6e-3f;   // (0.03*2)^2
    float lsum = 0.f;
#pragma unroll
    for (int k = 0; k < 4; k++) {
        float m1 = mu1[k], m2 = mu2[k];
        float m1sq = m1 * m1;
        float m2sq = m2 * m2;
        float m12  = m1 * m2;
        float s1c  = ex2[k] - m1sq;
        float s2c  = ey2[k] - m2sq;
        float s12  = exy[k] - m12;
        float num  = (2.f * m12 + C1) * (2.f * s12 + C2);
        float den  = (m1sq + m2sq + C1) * (s1c + s2c + C2);
        lsum += __fdividef(num, den + 1e-8f);
    }

    // ---- block reduction -> one double atomic per block ----
#pragma unroll
    for (int o = 16; o > 0; o >>= 1)
        lsum += __shfl_xor_sync(0xFFFFFFFFu, lsum, o);
    if ((tid & 31) == 0) wsum[tid >> 5] = lsum;
    __syncthreads();
    if (tid == 0) {
        float b = 0.f;
#pragma unroll
        for (int i = 0; i < 8; i++) b += wsum[i];
        atomicAdd(acc, (double)b);
    }
}

// Level 0 (512^2), fused pool -> A (256^2)
__global__ __launch_bounds__(256, 5) void ssim_l0_kernel(
    const float* __restrict__ X, const float* __restrict__ Y,
    double* __restrict__ acc, float* __restrict__ PX, float* __restrict__ PY)
{
    ssim_tile<true>(X, Y, 512, 512, blockIdx.x, blockIdx.y, blockIdx.z, acc, PX, PY);
}

// Merged tail: all 85 tiles/image of levels 1..4 in one launch.
__global__ __launch_bounds__(256, 5) void ssim_tail_kernel(
    const float* __restrict__ Ax, const float* __restrict__ Ay,
    const float* __restrict__ Bx, const float* __restrict__ By,
    const float* __restrict__ Cx, const float* __restrict__ Cy,
    const float* __restrict__ Dx, const float* __restrict__ Dy,
    double* __restrict__ acc)
{
    int bx = blockIdx.x;
    const float *X, *Y;
    int H, tx, ty, lvl;
    if (bx < 64)      { lvl = 1; H = 256; tx = bx & 7;  ty = bx >> 3;            X = Ax; Y = Ay; }
    else if (bx < 80) { lvl = 2; H = 128; int b = bx - 64; tx = b & 3; ty = b >> 2; X = Bx; Y = By; }
    else if (bx < 84) { lvl = 3; H = 64;  int b = bx - 80; tx = b & 1; ty = b >> 1; X = Cx; Y = Cy; }
    else              { lvl = 4; H = 32;  tx = 0; ty = 0;                          X = Dx; Y = Dy; }
    ssim_tile<false>(X, Y, H, H, tx, ty, blockIdx.z, acc + lvl, nullptr, nullptr);
}

// Local pyramid: each block pools its 64x64 region of A (256^2) down to
// B (128^2), C (64^2), D (32^2) entirely in smem. grid (4,4,NIMG).
__global__ __launch_bounds__(256) void pooltree_kernel(
    const float* __restrict__ Ax, const float* __restrict__ Ay,
    float* __restrict__ Bx, float* __restrict__ By,
    float* __restrict__ Cx, float* __restrict__ Cy,
    float* __restrict__ Dx, float* __restrict__ Dy)
{
    __shared__ float2 p1[32][33];
    __shared__ float2 p2[16][17];
    const int tid = threadIdx.x;
    const int img = blockIdx.z;
    const int rx  = blockIdx.x, ry = blockIdx.y;

    const float* ax = Ax + img * 256 * 256;
    const float* ay = Ay + img * 256 * 256;

    // pool A(64x64 region) -> 32x32, 4 outputs/thread
#pragma unroll
    for (int j = 0; j < 4; j++) {
        int o = tid + j * 256;            // 0..1023
        int r = o >> 5, c = o & 31;
        int gr = ry * 64 + 2 * r, gc = rx * 64 + 2 * c;
        float2 a = *(const float2*)&ax[gr * 256 + gc];
        float2 b = *(const float2*)&ax[(gr + 1) * 256 + gc];
        float2 e = *(const float2*)&ay[gr * 256 + gc];
        float2 f = *(const float2*)&ay[(gr + 1) * 256 + gc];
        float px = 0.25f * (a.x + a.y + b.x + b.y);
        float py = 0.25f * (e.x + e.y + f.x + f.y);
        int ob = img * 128 * 128 + (ry * 32 + r) * 128 + rx * 32 + c;
        Bx[ob] = px;
        By[ob] = py;
        p1[r][c] = make_float2(px, py);
    }
    __syncthreads();

    // 32x32 -> 16x16, 1 output/thread
    {
        int r = tid >> 4, c = tid & 15;
        float2 a = p1[2 * r][2 * c], b = p1[2 * r][2 * c + 1];
        float2 d = p1[2 * r + 1][2 * c], e = p1[2 * r + 1][2 * c + 1];
        float px = 0.25f * (a.x + b.x + d.x + e.x);
        float py = 0.25f * (a.y + b.y + d.y + e.y);
        int oc = img * 64 * 64 + (ry * 16 + r) * 64 + rx * 16 + c;
        Cx[oc] = px;
        Cy[oc] = py;
        p2[r][c] = make_float2(px, py);
    }
    __syncthreads();

    // 16x16 -> 8x8
    if (tid < 64) {
        int r = tid >> 3, c = tid & 7;
        float2 a = p2[2 * r][2 * c], b = p2[2 * r][2 * c + 1];
        float2 d = p2[2 * r + 1][2 * c], e = p2[2 * r + 1][2 * c + 1];
        int od = img * 32 * 32 + (ry * 8 + r) * 32 + rx * 8 + c;
        Dx[od] = 0.25f * (a.x + b.x + d.x + e.x);
        Dy[od] = 0.25f * (a.y + b.y + d.y + e.y);
    }
}

__global__ void finish_kernel(float* __restrict__ out) {
    const double w[5] = {0.0448, 0.2856, 0.3001, 0.2363, 0.1333};
    const double wsumv = 1.0001;  // reference normalizes by the weight sum
    double cnt = (double)NIMG * 512.0 * 512.0;
    double m = 0.0;
#pragma unroll
    for (int l = 0; l < 5; l++) {
        m += (w[l] / wsumv) * (g_acc[l] / cnt);
        cnt *= 0.25;
    }
    out[0] = (float)(1.0 - m);
}

extern "C" void kernel_launch(void* const* d_in, const int* in_sizes, int n_in,
                              void* d_out, int out_size)
{
    (void)in_sizes; (void)n_in; (void)out_size;
    const float* pred   = (const float*)d_in[0];
    const float* target = (const float*)d_in[1];
    float* out = (float*)d_out;

    float *bAx, *bAy, *bBx, *bBy, *bCx, *bCy, *bDx, *bDy;
    double* acc;
    cudaGetSymbolAddress((void**)&bAx, g_bufAx);
    cudaGetSymbolAddress((void**)&bAy, g_bufAy);
    cudaGetSymbolAddress((void**)&bBx, g_bufBx);
    cudaGetSymbolAddress((void**)&bBy, g_bufBy);
    cudaGetSymbolAddress((void**)&bCx, g_bufCx);
    cudaGetSymbolAddress((void**)&bCy, g_bufCy);
    cudaGetSymbolAddress((void**)&bDx, g_bufDx);
    cudaGetSymbolAddress((void**)&bDy, g_bufDy);
    cudaGetSymbolAddress((void**)&acc, g_acc);

    zero_acc_kernel<<<1, 32>>>();

    // L0: SSIM + fused pool -> A (256^2)
    ssim_l0_kernel<<<dim3(16, 16, NIMG), 256>>>(pred, target, acc, bAx, bAy);

    // Build remaining pyramid locally: A -> B, C, D
    pooltree_kernel<<<dim3(4, 4, NIMG), 256>>>(bAx, bAy, bBx, bBy, bCx, bCy, bDx, bDy);

    // Levels 1..4 merged into a single launch (85 tiles per image)
    ssim_tail_kernel<<<dim3(85, 1, NIMG), 256>>>(bAx, bAy, bBx, bBy, bCx, bCy, bDx, bDy, acc);

    finish_kernel<<<1, 1>>>(out);
}

// round 5
// speedup vs baseline: 1.2382x; 1.1618x over previous
#include <cuda_runtime.h>

#define R     5
#define TILE  32
#define HT    42          // TILE + 2*R
#define NIMG  48          // 16 batch * 3 channels (depthwise -> independent planes)

// Normalized 11-tap Gaussian (sigma=1.5) as compile-time literals
__device__ __forceinline__ float gw(int t) {
    constexpr float W[11] = {
        0.00102838f, 0.00759876f, 0.03600075f, 0.10936071f, 0.21300558f,
        0.26601173f,
        0.21300558f, 0.10936071f, 0.03600075f, 0.00759876f, 0.00102838f
    };
    return W[t];
}

// Pyramid in (s,d) space: s=x+y, d=x-y, interleaved float2.
__device__ float2 g_pyrA[NIMG * 256 * 256];   // level 1
__device__ float2 g_pyrB[NIMG * 128 * 128];   // level 2
__device__ float2 g_pyrC[NIMG * 64 * 64];     // level 3
__device__ float2 g_pyrD[NIMG * 32 * 32];     // level 4
__device__ double g_acc[5];

__global__ void zero_acc_kernel() {
    if (threadIdx.x < 5) g_acc[threadIdx.x] = 0.0;
}

// One 32x32 SSIM tile in (s,d) space.
// Pass 1: vertical blur of {s, d, s^2, d^2}, 4-row units (min smem reads).
// Pass 2: horizontal blur via LDS.128 on (S,D) and (P,Q) pairs, SSIM, reduce.
template<bool POOL, bool SD_IN>
__device__ __forceinline__ void ssim_tile(
    const float* __restrict__ X, const float* __restrict__ Y,   // SD_IN=false
    const float2* __restrict__ XY,                              // SD_IN=true
    int H, int W, int tx, int ty, int img,
    double* __restrict__ acc, float2* __restrict__ PO)
{
    __shared__ __align__(16) float2 sxy[HT][43];     // (s, d)
    __shared__ __align__(16) float2 hbSD[TILE][44];  // v-blurred (s, d)
    __shared__ __align__(16) float2 hbPQ[TILE][44];  // v-blurred (s^2, d^2)
    __shared__ float wsum[8];

    const int tid  = threadIdx.x;
    const int base = img * H * W;
    const int r0   = ty * TILE - R;
    const int c0   = tx * TILE - R;

    // ---- load tile + halo (zero padding outside image) ----
    for (int i = tid; i < HT * HT; i += 256) {
        int r  = i / HT, c = i - r * HT;
        int gr = r0 + r, gc = c0 + c;
        float sv = 0.0f, dv = 0.0f;
        if ((unsigned)gr < (unsigned)H && (unsigned)gc < (unsigned)W) {
            int gi = base + gr * W + gc;
            if (SD_IN) {
                float2 v = XY[gi];
                sv = v.x; dv = v.y;
            } else {
                float xv = X[gi], yv = Y[gi];
                sv = xv + yv; dv = xv - yv;
            }
        }
        sxy[r][c] = make_float2(sv, dv);
    }
    __syncthreads();

    // ---- fused 2x2 avg-pool of the central 32x32 (next level's input) ----
    if (POOL) {
        int pr = tid >> 4, pc = tid & 15;
        int rr = R + 2 * pr, cc = R + 2 * pc;
        float2 a = sxy[rr][cc],     b = sxy[rr][cc + 1];
        float2 c = sxy[rr + 1][cc], d = sxy[rr + 1][cc + 1];
        int Ho = H >> 1, Wo = W >> 1;
        int o  = img * Ho * Wo + (ty * 16 + pr) * Wo + tx * 16 + pc;
        PO[o] = make_float2(0.25f * (a.x + b.x + c.x + d.x),
                            0.25f * (a.y + b.y + c.y + d.y));
    }

    // ---- pass 1: vertical blur, 4 output rows per unit (336 units) ----
    for (int u = tid; u < HT * 8; u += 256) {
        int c  = u % HT;
        int rb = (u / HT) * 4;
        float aS[4] = {}, aD[4] = {}, aP[4] = {}, aQ[4] = {};
#pragma unroll
        for (int t = 0; t < 14; t++) {
            float2 v = sxy[rb + t][c];
            float s2 = v.x * v.x, d2 = v.y * v.y;
#pragma unroll
            for (int k = 0; k < 4; k++) {
                int tt = t - k;                 // compile-time after unroll
                if (tt >= 0 && tt <= 10) {
                    float w = gw(tt);
                    aS[k] += w * v.x;
                    aD[k] += w * v.y;
                    aP[k] += w * s2;
                    aQ[k] += w * d2;
                }
            }
        }
#pragma unroll
        for (int k = 0; k < 4; k++) {
            hbSD[rb + k][c] = make_float2(aS[k], aD[k]);
            hbPQ[rb + k][c] = make_float2(aP[k], aQ[k]);
        }
    }
    __syncthreads();

    // ---- pass 2: horizontal blur + SSIM, 4 px/thread ----
    const int vr = tid >> 3;          // output row 0..31
    const int vc = (tid & 7) * 4;     // output col group (16B aligned)

    float mS[4] = {}, mD[4] = {}, mP[4] = {}, mQ[4] = {};

    {   // (S, D) stream — 7 x LDS.128
        float2 v[14];
        const float4* p = (const float4*)&hbSD[vr][vc];
#pragma unroll
        for (int q = 0; q < 7; q++) {
            float4 a = p[q];
            v[2 * q]     = make_float2(a.x, a.y);
            v[2 * q + 1] = make_float2(a.z, a.w);
        }
#pragma unroll
        for (int t = 0; t < 14; t++)
#pragma unroll
            for (int k = 0; k < 4; k++) {
                int tt = t - k;
                if (tt >= 0 && tt <= 10) {
                    mS[k] += gw(tt) * v[t].x;
                    mD[k] += gw(tt) * v[t].y;
                }
            }
    }
    {   // (P, Q) stream — 7 x LDS.128
        float2 v[14];
        const float4* p = (const float4*)&hbPQ[vr][vc];
#pragma unroll
        for (int q = 0; q < 7; q++) {
            float4 a = p[q];
            v[2 * q]     = make_float2(a.x, a.y);
            v[2 * q + 1] = make_float2(a.z, a.w);
        }
#pragma unroll
        for (int t = 0; t < 14; t++)
#pragma unroll
            for (int k = 0; k < 4; k++) {
                int tt = t - k;
                if (tt >= 0 && tt <= 10) {
                    mP[k] += gw(tt) * v[t].x;
                    mQ[k] += gw(tt) * v[t].y;
                }
            }
    }

    const float C1 = 4.0e-4f;   // (0.01*2)^2
    const float C2 = 3.6e-3f;   // (0.03*2)^2
    float lsum = 0.f;
#pragma unroll
    for (int k = 0; k < 4; k++) {
        float S2 = mS[k] * mS[k];
        float D2 = mD[k] * mD[k];
        float sumSq  = 0.5f * (S2 + D2);           // mu1^2 + mu2^2
        float difSq  = 0.5f * (S2 - D2);           // 2*mu1*mu2
        float A1 = difSq + C1;
        float B1 = sumSq + C1;
        float A2 = 0.5f * (mP[k] - mQ[k]) - difSq + C2;   // 2*sig12 + C2
        float B2 = 0.5f * (mP[k] + mQ[k]) - sumSq + C2;   // sig1+sig2 + C2
        lsum += __fdividef(A1 * A2, B1 * B2 + 1e-8f);
    }

    // ---- block reduction -> one double atomic per block ----
#pragma unroll
    for (int o = 16; o > 0; o >>= 1)
        lsum += __shfl_xor_sync(0xFFFFFFFFu, lsum, o);
    if ((tid & 31) == 0) wsum[tid >> 5] = lsum;
    __syncthreads();
    if (tid == 0) {
        float b = 0.f;
#pragma unroll
        for (int i = 0; i < 8; i++) b += wsum[i];
        atomicAdd(acc, (double)b);
    }
}

// Level 0 (512^2), fused pool -> pyrA (256^2, s/d space)
__global__ __launch_bounds__(256, 5) void ssim_l0_kernel(
    const float* __restrict__ X, const float* __restrict__ Y,
    double* __restrict__ acc, float2* __restrict__ PO)
{
    ssim_tile<true, false>(X, Y, nullptr, 512, 512,
                           blockIdx.x, blockIdx.y, blockIdx.z, acc, PO);
}

// Merged tail: all 85 tiles/image of levels 1..4 in one launch.
__global__ __launch_bounds__(256, 5) void ssim_tail_kernel(
    const float2* __restrict__ A, const float2* __restrict__ B,
    const float2* __restrict__ C, const float2* __restrict__ D,
    double* __restrict__ acc)
{
    int bx = blockIdx.x;
    const float2* XY;
    int H, tx, ty, lvl;
    if (bx < 64)      { lvl = 1; H = 256; tx = bx & 7;  ty = bx >> 3;              XY = A; }
    else if (bx < 80) { lvl = 2; H = 128; int b = bx - 64; tx = b & 3; ty = b >> 2; XY = B; }
    else if (bx < 84) { lvl = 3; H = 64;  int b = bx - 80; tx = b & 1; ty = b >> 1; XY = C; }
    else              { lvl = 4; H = 32;  tx = 0; ty = 0;                           XY = D; }
    ssim_tile<false, true>(nullptr, nullptr, XY, H, H, tx, ty, blockIdx.z,
                           acc + lvl, nullptr);
}

// Local pyramid: each block pools its 64x64 region of A (256^2) down to
// B (128^2), C (64^2), D (32^2) entirely in smem. grid (4,4,NIMG).
__global__ __launch_bounds__(256) void pooltree_kernel(
    const float2* __restrict__ A, float2* __restrict__ B,
    float2* __restrict__ C, float2* __restrict__ D)
{
    __shared__ float2 p1[32][33];
    __shared__ float2 p2[16][17];
    const int tid = threadIdx.x;
    const int img = blockIdx.z;
    const int rx  = blockIdx.x, ry = blockIdx.y;

    const float2* a0 = A + img * 256 * 256;

    // pool A(64x64 region) -> 32x32, 4 outputs/thread
#pragma unroll
    for (int j = 0; j < 4; j++) {
        int o = tid + j * 256;            // 0..1023
        int r = o >> 5, c = o & 31;
        int gr = ry * 64 + 2 * r, gc = rx * 64 + 2 * c;
        float2 a = a0[gr * 256 + gc],       b = a0[gr * 256 + gc + 1];
        float2 e = a0[(gr + 1) * 256 + gc], f = a0[(gr + 1) * 256 + gc + 1];
        float2 pv = make_float2(0.25f * (a.x + b.x + e.x + f.x),
                                0.25f * (a.y + b.y + e.y + f.y));
        int ob = img * 128 * 128 + (ry * 32 + r) * 128 + rx * 32 + c;
        B[ob] = pv;
        p1[r][c] = pv;
    }
    __syncthreads();

    // 32x32 -> 16x16, 1 output/thread
    {
        int r = tid >> 4, c = tid & 15;
        float2 a = p1[2 * r][2 * c],     b = p1[2 * r][2 * c + 1];
        float2 d = p1[2 * r + 1][2 * c], e = p1[2 * r + 1][2 * c + 1];
        float2 pv = make_float2(0.25f * (a.x + b.x + d.x + e.x),
                                0.25f * (a.y + b.y + d.y + e.y));
        int oc = img * 64 * 64 + (ry * 16 + r) * 64 + rx * 16 + c;
        C[oc] = pv;
        p2[r][c] = pv;
    }
    __syncthreads();

    // 16x16 -> 8x8
    if (tid < 64) {
        int r = tid >> 3, c = tid & 7;
        float2 a = p2[2 * r][2 * c],     b = p2[2 * r][2 * c + 1];
        float2 d = p2[2 * r + 1][2 * c], e = p2[2 * r + 1][2 * c + 1];
        int od = img * 32 * 32 + (ry * 8 + r) * 32 + rx * 8 + c;
        D[od] = make_float2(0.25f * (a.x + b.x + d.x + e.x),
                            0.25f * (a.y + b.y + d.y + e.y));
    }
}

__global__ void finish_kernel(float* __restrict__ out) {
    const double w[5] = {0.0448, 0.2856, 0.3001, 0.2363, 0.1333};
    const double wsumv = 1.0001;  // reference normalizes by the weight sum
    double cnt = (double)NIMG * 512.0 * 512.0;
    double m = 0.0;
#pragma unroll
    for (int l = 0; l < 5; l++) {
        m += (w[l] / wsumv) * (g_acc[l] / cnt);
        cnt *= 0.25;
    }
    out[0] = (float)(1.0 - m);
}

extern "C" void kernel_launch(void* const* d_in, const int* in_sizes, int n_in,
                              void* d_out, int out_size)
{
    (void)in_sizes; (void)n_in; (void)out_size;
    const float* pred   = (const float*)d_in[0];
    const float* target = (const float*)d_in[1];
    float* out = (float*)d_out;

    float2 *pA, *pB, *pC, *pD;
    double* acc;
    cudaGetSymbolAddress((void**)&pA, g_pyrA);
    cudaGetSymbolAddress((void**)&pB, g_pyrB);
    cudaGetSymbolAddress((void**)&pC, g_pyrC);
    cudaGetSymbolAddress((void**)&pD, g_pyrD);
    cudaGetSymbolAddress((void**)&acc, g_acc);

    zero_acc_kernel<<<1, 32>>>();

    // L0: SSIM + fused pool -> A (256^2, s/d space)
    ssim_l0_kernel<<<dim3(16, 16, NIMG), 256>>>(pred, target, acc, pA);

    // Build remaining pyramid locally: A -> B, C, D
    pooltree_kernel<<<dim3(4, 4, NIMG), 256>>>(pA, pB, pC, pD);

    // Levels 1..4 merged into a single launch (85 tiles per image)
    ssim_tail_kernel<<<dim3(85, 1, NIMG), 256>>>(pA, pB, pC, pD, acc);

    finish_kernel<<<1, 1>>>(out);
}